// round 11
// baseline (speedup 1.0000x reference)
#include <cuda_runtime.h>
#include <cuda_fp16.h>
#include <math.h>
#include <stdint.h>

// Problem constants
#define BDIM   32
#define NTRAJ  512
#define LAT    256
#define HID    1024
#define TSTEPS 10
// The ODE is row-local: tanh(x@W1+b1)@W2 never couples rows. The corrcoef
// block (rows 512..767 per batch) is discarded by the final slice, so we
// only evolve the 512 trajectory rows per batch.
#define MTOT   (BDIM * NTRAJ)       // 16384 rows

// ---------------- scratch ----------------------------------------------------
__device__ __align__(16) float  g_x   [MTOT * LAT];   // committed state (fp32)
__device__ __align__(16) float  g_ksum[MTOT * LAT];   // weighted k accum (fp32)
__device__ __align__(16) __half g_xin [MTOT * LAT];   // next eval input (fp16)
__device__ __align__(16) __half g_h   [MTOT * HID];   // hidden (fp16)
__device__ __align__(16) __half g_W1T [HID * LAT];    // W1^T [n=1024][k=256]
__device__ __align__(16) __half g_W2T [LAT * HID];    // W2^T [n=256][k=1024]

// ---------------- helpers -----------------------------------------------------
__device__ __forceinline__ float tanh_fast(float x) {
    float y;
    asm("tanh.approx.f32 %0, %1;" : "=f"(y) : "f"(x));
    return y;
}

__device__ __forceinline__ void mma_fp16(float* d, const uint32_t* a,
                                         uint32_t b0, uint32_t b1) {
    asm("mma.sync.aligned.m16n8k16.row.col.f32.f16.f16.f32 "
        "{%0,%1,%2,%3},{%4,%5,%6,%7},{%8,%9},{%0,%1,%2,%3};"
        : "+f"(d[0]), "+f"(d[1]), "+f"(d[2]), "+f"(d[3])
        : "r"(a[0]), "r"(a[1]), "r"(a[2]), "r"(a[3]), "r"(b0), "r"(b1));
}

__device__ __forceinline__ void ldsm4(uint32_t* r, uint32_t addr) {
    asm volatile("ldmatrix.sync.aligned.m8n8.x4.shared.b16 {%0,%1,%2,%3}, [%4];"
                 : "=r"(r[0]), "=r"(r[1]), "=r"(r[2]), "=r"(r[3]) : "r"(addr));
}

__device__ __forceinline__ void cp16(uint32_t dst, const void* src) {
    asm volatile("cp.async.cg.shared.global [%0], [%1], 16;"
                 :: "r"(dst), "l"(src));
}
__device__ __forceinline__ void cp_commit() {
    asm volatile("cp.async.commit_group;" ::: "memory");
}
template<int N>
__device__ __forceinline__ void cp_wait() {
    asm volatile("cp.async.wait_group %0;" :: "n"(N) : "memory");
}

__device__ __forceinline__ uint32_t smem_u32(const void* p) {
    uint32_t a;
    asm("{ .reg .u64 t; cvta.to.shared.u64 t, %1; cvt.u32.u64 %0, t; }"
        : "=r"(a) : "l"(p));
    return a;
}

__device__ __forceinline__ uint32_t pack_h2(float lo, float hi) {
    uint32_t p;
    asm("cvt.rn.f16x2.f32 %0, %1, %2;" : "=r"(p) : "f"(hi), "f"(lo));
    return p;
}

// ---------------- setup kernels ----------------------------------------------
__global__ void k_init(const float* __restrict__ fp, float* __restrict__ out) {
    int i = blockIdx.x * blockDim.x + threadIdx.x;
    if (i >= MTOT * LAT) return;
    int c = i % LAT;
    int row = i / LAT;          // = b*NTRAJ + n
    float v = fp[i];
    g_x[i] = v;
    g_xin[i] = __float2half(v);
    out[((size_t)row * TSTEPS + 0) * LAT + c] = v;
}

__global__ void k_w1t(const float* __restrict__ W1) {
    int i = blockIdx.x * blockDim.x + threadIdx.x;
    if (i >= LAT * HID) return;
    int k = i / HID, n = i % HID;
    g_W1T[(size_t)n * LAT + k] = __float2half(W1[i]);
}
__global__ void k_w2t(const float* __restrict__ W2) {
    int i = blockIdx.x * blockDim.x + threadIdx.x;
    if (i >= HID * LAT) return;
    int k = i / LAT, n = i % LAT;
    g_W2T[(size_t)n * HID + k] = __float2half(W2[i]);
}

// ---------------- fp16 GEMM: 256x128 tile, 512 thr, warp 64x32 ---------------
// 16 warps: 4 in m (64 rows each) x 4 in n (32 cols each).
// k-chunk = 64 halfs per stage (128B payload/row, 144B padded rows).
// 3-stage cp.async pipeline, ldmatrix.x4, software-pipelined fragments.
//
// IS_G1: A=g_xin (K=256), B=g_W1T, epilogue tanh(.+b1) -> g_h
// else : A=g_h   (K=1024), B=g_W2T, epilogue RK4 bookkeeping (mode 0/1/2)
#define ROWP      144                  // padded smem row bytes
#define TILE_A    (256 * ROWP)         // 36864 B
#define TILE_Bb   (128 * ROWP)         // 18432 B
#define STG_BYTES (TILE_A + TILE_Bb)   // 55296 B
#define SMEM_TOT  (3 * STG_BYTES)      // 165888 B

template<int KDIM, bool IS_G1>
__global__ __launch_bounds__(512, 1)
void k_mm(const float* __restrict__ b1v, const float* __restrict__ ts, int step,
          int mode, float cnext, float* __restrict__ out) {
    constexpr int NIT  = KDIM / 64;
    constexpr int ROWB = KDIM * 2;

    extern __shared__ __align__(16) char sm[];
    const uint32_t smB = smem_u32(sm);

    const int m0 = blockIdx.y * 256;
    const int n0 = blockIdx.x * 128;
    const int tid  = threadIdx.x;
    const int lane = tid & 31;
    const int warp = tid >> 5;
    const int wm = warp & 3;            // m quarter (64 rows)
    const int wn = warp >> 2;           // n quarter (32 cols)
    const int r  = lane >> 2;
    const int cq = lane & 3;

    // ldmatrix per-lane address parts
    const int sub = lane >> 3;
    const int rowPart = ((sub & 1) * 8 + (lane & 7));
    const int colPart = (sub >> 1) * 16;

    // cp.async mapping: A 4 cp16/thread (256 rows), B 2 cp16/thread (128 rows)
    const int cRow0 = tid >> 3;         // 0..63
    const int cSeg  = tid & 7;

    const char* Ag = (const char*)(IS_G1 ? g_xin : g_h)
                   + (size_t)m0 * ROWB + cSeg * 16;
    const char* Bg = (const char*)(IS_G1 ? g_W1T : g_W2T)
                   + (size_t)n0 * ROWB + cSeg * 16;

    auto copyStage = [&](int it, int s) {
        uint32_t so = smB + (uint32_t)s * STG_BYTES;
        #pragma unroll
        for (int o = 0; o < 4; o++) {
            int row = cRow0 + o * 64;
            cp16(so + row * ROWP + cSeg * 16,
                 Ag + (size_t)row * ROWB + it * 128);
        }
        #pragma unroll
        for (int o = 0; o < 2; o++) {
            int row = cRow0 + o * 64;
            cp16(so + TILE_A + row * ROWP + cSeg * 16,
                 Bg + (size_t)row * ROWB + it * 128);
        }
        cp_commit();
    };

    float acc[4][4][4] = {};

    copyStage(0, 0);
    copyStage(1, 1);

    #pragma unroll 1
    for (int it = 0; it < NIT; it++) {
        if (it + 1 < NIT) cp_wait<1>(); else cp_wait<0>();
        __syncthreads();
        if (it + 2 < NIT) copyStage(it + 2, (it + 2) % 3);

        const uint32_t aBase = smB + (uint32_t)(it % 3) * STG_BYTES
                             + (wm * 64 + rowPart) * ROWP + colPart;
        const uint32_t bBase = smB + (uint32_t)(it % 3) * STG_BYTES + TILE_A
                             + (wn * 32 + rowPart) * ROWP + colPart;

        uint32_t bq[2][8], af[2][4];
        ldsm4(bq[0],     bBase);
        ldsm4(bq[0] + 4, bBase + 16 * ROWP);
        ldsm4(af[0],     aBase);

        #pragma unroll
        for (int kq = 0; kq < 4; kq++) {
            const int kb = kq & 1;
            #pragma unroll
            for (int mt = 0; mt < 4; mt++) {
                if (mt < 3) {
                    ldsm4(af[(mt + 1) & 1], aBase + (mt + 1) * (16 * ROWP) + kq * 32);
                } else if (kq < 3) {
                    ldsm4(bq[kb ^ 1],     bBase + (kq + 1) * 32);
                    ldsm4(bq[kb ^ 1] + 4, bBase + 16 * ROWP + (kq + 1) * 32);
                    ldsm4(af[0],          aBase + (kq + 1) * 32);
                }
                const uint32_t* B = bq[kb];
                const uint32_t* A = af[mt & 1];
                mma_fp16(acc[mt][0], A, B[0], B[2]);
                mma_fp16(acc[mt][1], A, B[1], B[3]);
                mma_fp16(acc[mt][2], A, B[4], B[6]);
                mma_fp16(acc[mt][3], A, B[5], B[7]);
            }
        }
    }

    // ---------------- epilogue ----------------
    if (IS_G1) {
        #pragma unroll
        for (int mt = 0; mt < 4; mt++) {
            int row0 = m0 + wm * 64 + mt * 16 + r;
            #pragma unroll
            for (int nt = 0; nt < 4; nt++) {
                int col = n0 + wn * 32 + nt * 8 + 2 * cq;
                float bx = __ldg(b1v + col), by = __ldg(b1v + col + 1);
                float t0 = tanh_fast(acc[mt][nt][0] + bx);
                float t1 = tanh_fast(acc[mt][nt][1] + by);
                float t2 = tanh_fast(acc[mt][nt][2] + bx);
                float t3 = tanh_fast(acc[mt][nt][3] + by);
                *(uint32_t*)((char*)g_h + ((size_t)row0 * HID + col) * 2)
                    = pack_h2(t0, t1);
                *(uint32_t*)((char*)g_h + ((size_t)(row0 + 8) * HID + col) * 2)
                    = pack_h2(t2, t3);
            }
        }
    } else {
        const float dt = ts[step + 1] - ts[step];
        const float cn = cnext * dt;
        const float s6 = dt * (1.0f / 6.0f);

        #pragma unroll
        for (int mt = 0; mt < 4; mt++) {
            #pragma unroll
            for (int h = 0; h < 2; h++) {
                int row = m0 + wm * 64 + mt * 16 + r + 8 * h;   // = b*NTRAJ + n
                #pragma unroll
                for (int nt = 0; nt < 4; nt++) {
                    int col = n0 + wn * 32 + nt * 8 + 2 * cq;
                    float v0 = acc[mt][nt][2 * h + 0];
                    float v1 = acc[mt][nt][2 * h + 1];
                    size_t idx = (size_t)row * LAT + col;
                    if (mode == 0) {
                        g_ksum[idx] = v0;  g_ksum[idx + 1] = v1;
                        float xi0 = fmaf(cn, v0, g_x[idx]);
                        float xi1 = fmaf(cn, v1, g_x[idx + 1]);
                        *(uint32_t*)((char*)g_xin + idx * 2) = pack_h2(xi0, xi1);
                    } else if (mode == 1) {
                        g_ksum[idx]     += 2.f * v0;
                        g_ksum[idx + 1] += 2.f * v1;
                        float xi0 = fmaf(cn, v0, g_x[idx]);
                        float xi1 = fmaf(cn, v1, g_x[idx + 1]);
                        *(uint32_t*)((char*)g_xin + idx * 2) = pack_h2(xi0, xi1);
                    } else {
                        float x0 = g_x[idx] + s6 * (g_ksum[idx] + v0);
                        float x1 = g_x[idx + 1] + s6 * (g_ksum[idx + 1] + v1);
                        g_x[idx] = x0;   g_x[idx + 1] = x1;
                        *(uint32_t*)((char*)g_xin + idx * 2) = pack_h2(x0, x1);
                        size_t o = ((size_t)row * TSTEPS + (step + 1)) * LAT + col;
                        out[o] = x0; out[o + 1] = x1;
                    }
                }
            }
        }
    }
}

// ---------------- launch ------------------------------------------------------
extern "C" void kernel_launch(void* const* d_in, const int* in_sizes, int n_in,
                              void* d_out, int out_size) {
    const float* fp = (const float*)d_in[0];
    const float* ts = (const float*)d_in[1];
    const float* W1 = (const float*)d_in[2];
    const float* b1 = (const float*)d_in[3];
    const float* W2 = (const float*)d_in[4];
    float* out = (float*)d_out;

    static int attr_done = 0;
    if (!attr_done) {
        cudaFuncSetAttribute(k_mm<LAT, true>,
                             cudaFuncAttributeMaxDynamicSharedMemorySize, SMEM_TOT);
        cudaFuncSetAttribute(k_mm<HID, false>,
                             cudaFuncAttributeMaxDynamicSharedMemorySize, SMEM_TOT);
        attr_done = 1;
    }

    k_init<<<(MTOT * LAT + 255) / 256, 256>>>(fp, out);
    k_w1t<<<(LAT * HID + 255) / 256, 256>>>(W1);
    k_w2t<<<(HID * LAT + 255) / 256, 256>>>(W2);

    dim3 g1(HID / 128, MTOT / 256);   // (8, 64) = 512 blocks
    dim3 g2(LAT / 128, MTOT / 256);   // (2, 64) = 128 blocks

    for (int s = 0; s < TSTEPS - 1; s++) {
        // eval 1 -> k1: ksum = k1,  xin = x + 0.5*dt*k1
        k_mm<LAT,  true ><<<g1, 512, SMEM_TOT>>>(b1, ts, s, 0, 0.0f, nullptr);
        k_mm<HID,  false><<<g2, 512, SMEM_TOT>>>(nullptr, ts, s, 0, 0.5f, out);
        // eval 2 -> k2: ksum += 2*k2, xin = x + 0.5*dt*k2
        k_mm<LAT,  true ><<<g1, 512, SMEM_TOT>>>(b1, ts, s, 0, 0.0f, nullptr);
        k_mm<HID,  false><<<g2, 512, SMEM_TOT>>>(nullptr, ts, s, 1, 0.5f, out);
        // eval 3 -> k3: ksum += 2*k3, xin = x + dt*k3
        k_mm<LAT,  true ><<<g1, 512, SMEM_TOT>>>(b1, ts, s, 0, 0.0f, nullptr);
        k_mm<HID,  false><<<g2, 512, SMEM_TOT>>>(nullptr, ts, s, 1, 1.0f, out);
        // eval 4 -> k4: x += dt/6*(ksum + k4); write slice; xin = x_new
        k_mm<LAT,  true ><<<g1, 512, SMEM_TOT>>>(b1, ts, s, 0, 0.0f, nullptr);
        k_mm<HID,  false><<<g2, 512, SMEM_TOT>>>(nullptr, ts, s, 2, 0.0f, out);
    }
}